// round 15
// baseline (speedup 1.0000x reference)
#include <cuda_runtime.h>
#include <math.h>
#include <stdint.h>

#define DIMK 64
#define NN 16
#define BATCH 4096
#define NRELT 33
#define NT 256
#define NITEMS 2
#define GRID (BATCH / NITEMS)
#define RST 80   // swizzled row stride in floats

__device__ float g_eurel[BATCH * NRELT];

struct PerItem {
    float e1v[NN * DIMK];     // 4 KB
    float xbuf[NN * RST];     // 5 KB, swizzled: chunk (kh,q) at float off kh*20+q*4
    float x0[RST];
    float x1[RST];
    float userv[DIMK];
    float e0v[DIMK];
    float outf[DIMK];
    float attn[NN * NN];      // 1 KB
    float urel[NRELT + 3];    // holds exp(user.rel)
    float attn0[NN];
    int   e2[NN * NN];        // 1 KB
    int   r2[NN * NN];        // 1 KB
    int   r1[NN];
};

struct Smem {
    PerItem pi[NITEMS];
    float b0[DIMK];
    float b1[DIMK];
};

__device__ __forceinline__ float fsigmoid(float x) {
    return __fdividef(1.0f, 1.0f + __expf(-x));
}

__device__ __forceinline__ uint64_t fma2(uint64_t a, uint64_t b, uint64_t c) {
    uint64_t d;
    asm("fma.rn.f32x2 %0, %1, %2, %3;" : "=l"(d) : "l"(a), "l"(b), "l"(c));
    return d;
}
__device__ __forceinline__ uint64_t pack2(float lo, float hi) {
    uint64_t d;
    asm("mov.b64 %0, {%1, %2};" : "=l"(d) : "f"(lo), "f"(hi));
    return d;
}
__device__ __forceinline__ float hadd2(uint64_t a) {
    float lo, hi;
    asm("mov.b64 {%0, %1}, %2;" : "=f"(lo), "=f"(hi) : "l"(a));
    return lo + hi;
}

// Kernel A: g_eurel[item][r] = exp(user[item] . rel_emb[r])
__global__ __launch_bounds__(256)
void urel_kernel(const int* __restrict__ u,
                 const float* __restrict__ usr_emb,
                 const float* __restrict__ rel_emb)
{
    const int t = blockIdx.x * 256 + threadIdx.x;
    if (t >= BATCH * NRELT) return;
    const int item = t / NRELT;
    const int r = t - item * NRELT;
    const int uu = __ldg(u + item);
    const float4* u4 = reinterpret_cast<const float4*>(usr_emb) + uu * 16;
    const float4* r4 = reinterpret_cast<const float4*>(rel_emb) + r * 16;
    float acc = 0.f;
    #pragma unroll
    for (int q = 0; q < 16; ++q) {
        const float4 a = __ldg(u4 + q);
        const float4 b = __ldg(r4 + q);
        acc += a.x * b.x + a.y * b.y + a.z * b.z + a.w * b.w;
    }
    g_eurel[t] = __expf(acc);
}

__global__ __launch_bounds__(NT, 6)
void kgnn_kernel(const int* __restrict__ u, const int* __restrict__ v,
                 const int* __restrict__ adj, const int* __restrict__ rel_adj,
                 const float* __restrict__ usr_emb, const float* __restrict__ ent_emb,
                 const float* __restrict__ rel_emb,
                 const float* __restrict__ W0g, const float* __restrict__ b0g,
                 const float* __restrict__ W1g, const float* __restrict__ b1g,
                 float* __restrict__ out)
{
    extern __shared__ char smem_raw[];
    Smem& s = *reinterpret_cast<Smem*>(smem_raw);
    const int tid  = threadIdx.x;
    const int lane = tid & 31;
    const int warp = tid >> 5;
    const int c     = warp * 8 + (lane & 7);
    const int kh    = lane >> 3;
    const int kbase = kh * 16;
    const int kh20  = kh * 20;
    const bool kh0  = (kh == 0);

    const float4* ent4 = reinterpret_cast<const float4*>(ent_emb);
    const ulonglong2* ent8 = reinterpret_cast<const ulonglong2*>(ent_emb);
    const int item0 = blockIdx.x * NITEMS;

    uint64_t Wp[8];
    #pragma unroll
    for (int q = 0; q < 8; ++q)
        Wp[q] = pack2(__ldg(W0g + (kbase + 2 * q) * DIMK + c),
                      __ldg(W0g + (kbase + 2 * q + 1) * DIMK + c));
    if (tid < DIMK) { s.b0[tid] = b0g[tid]; s.b1[tid] = b1g[tid]; }
    __syncthreads();

    // ---- P1: indices + e1v staging + root vectors + eurel load (both items) ----
    #pragma unroll
    for (int ii = 0; ii < NITEMS; ++ii) {
        PerItem& p = s.pi[ii];
        const int vv = __ldg(v + item0 + ii);
        const int uu = __ldg(u + item0 + ii);
        const int m = tid >> 4, n = tid & 15;
        const int e1m = __ldg(adj + vv * NN + m);
        p.e2[tid] = __ldg(adj + e1m * NN + n);
        p.r2[tid] = __ldg(rel_adj + e1m * NN + n);
        reinterpret_cast<float4*>(p.e1v)[tid] = __ldg(ent4 + e1m * 16 + n);
        if (tid < NRELT)
            p.urel[tid] = __ldg(g_eurel + (item0 + ii) * NRELT + tid);
        if (tid < 16) {
            p.r1[tid] = __ldg(rel_adj + vv * NN + tid);
            reinterpret_cast<float4*>(p.userv)[tid] = __ldg(
                reinterpret_cast<const float4*>(usr_emb) + uu * 16 + tid);
        } else if (tid < 32) {
            reinterpret_cast<float4*>(p.e0v)[tid - 16] = __ldg(ent4 + vv * 16 + (tid - 16));
        }
    }
    __syncthreads();

    // ---- P2: softmax (exp precomputed; no max pass) ----
    #pragma unroll
    for (int ii = 0; ii < NITEMS; ++ii) {
        PerItem& p = s.pi[ii];
        const float e = p.urel[p.r2[tid]];
        float sum = e;
        #pragma unroll
        for (int off = 8; off > 0; off >>= 1)
            sum += __shfl_xor_sync(0xffffffffu, sum, off);
        p.attn[tid] = __fdividef(e, sum);

        if (warp == ii) {
            const float e0 = p.urel[p.r1[lane & 15]];
            float s0 = e0;
            #pragma unroll
            for (int off = 8; off > 0; off >>= 1)
                s0 += __shfl_xor_sync(0xffffffffu, s0, off);
            if (lane < 16) p.attn0[lane] = __fdividef(e0, s0);
        }
    }
    __syncthreads();

    // ---- P3: hop-1 aggregation + x0 on warps 6/7; swizzled stores ----
    #pragma unroll
    for (int ii = 0; ii < NITEMS; ++ii) {
        PerItem& p = s.pi[ii];
        const int m  = warp * 2 + (lane >> 4);
        const int l4 = lane & 15;
        const int swoff = (l4 >> 2) * 20 + (l4 & 3) * 4;
        const int4*   e2v = reinterpret_cast<const int4*>(p.e2 + m * NN);
        const float4* av  = reinterpret_cast<const float4*>(p.attn + m * NN);
        ulonglong2 acc = reinterpret_cast<const ulonglong2*>(p.e1v + m * DIMK)[l4];
        #pragma unroll
        for (int j = 0; j < 4; ++j) {
            const int4   ei = e2v[j];
            const float4 aw = av[j];
            const uint64_t a0 = pack2(aw.x, aw.x);
            const uint64_t a1 = pack2(aw.y, aw.y);
            const uint64_t a2 = pack2(aw.z, aw.z);
            const uint64_t a3 = pack2(aw.w, aw.w);
            const ulonglong2 v0 = __ldg(ent8 + ei.x * 16 + l4);
            const ulonglong2 v1 = __ldg(ent8 + ei.y * 16 + l4);
            const ulonglong2 v2 = __ldg(ent8 + ei.z * 16 + l4);
            const ulonglong2 v3 = __ldg(ent8 + ei.w * 16 + l4);
            acc.x = fma2(a0, v0.x, acc.x); acc.y = fma2(a0, v0.y, acc.y);
            acc.x = fma2(a1, v1.x, acc.x); acc.y = fma2(a1, v1.y, acc.y);
            acc.x = fma2(a2, v2.x, acc.x); acc.y = fma2(a2, v2.y, acc.y);
            acc.x = fma2(a3, v3.x, acc.x); acc.y = fma2(a3, v3.y, acc.y);
        }
        *reinterpret_cast<ulonglong2*>(p.xbuf + m * RST + swoff) = acc;

        if (warp == 6 + ii && lane < 16) {
            ulonglong2 a0v = reinterpret_cast<const ulonglong2*>(p.e0v)[lane];
            #pragma unroll
            for (int n = 0; n < NN; ++n) {
                const ulonglong2 ev = reinterpret_cast<const ulonglong2*>(p.e1v + n * DIMK)[lane];
                const float an = p.attn0[n];
                const uint64_t an2 = pack2(an, an);
                a0v.x = fma2(an2, ev.x, a0v.x);
                a0v.y = fma2(an2, ev.y, a0v.y);
            }
            *reinterpret_cast<ulonglong2*>(p.x0 + swoff) = a0v;
        }
    }
    __syncthreads();

    // ---- P4: fused GEMM ----
    #pragma unroll
    for (int ii = 0; ii < NITEMS; ++ii) {
        PerItem& p = s.pi[ii];
        const float b0c = s.b0[c];
        float x1acc = 0.f;
        #pragma unroll
        for (int r = 0; r < NN; r += 2) {
            uint64_t p0 = 0, p1 = 0;
            const float* xr0 = p.xbuf + r * RST + kh20;
            const float* xr1 = p.xbuf + (r + 1) * RST + kh20;
            #pragma unroll
            for (int q = 0; q < 4; ++q) {
                const ulonglong2 xv0 = *reinterpret_cast<const ulonglong2*>(xr0 + q * 4);
                const ulonglong2 xv1 = *reinterpret_cast<const ulonglong2*>(xr1 + q * 4);
                p0 = fma2(xv0.x, Wp[2 * q + 0], p0);
                p1 = fma2(xv1.x, Wp[2 * q + 0], p1);
                p0 = fma2(xv0.y, Wp[2 * q + 1], p0);
                p1 = fma2(xv1.y, Wp[2 * q + 1], p1);
            }
            float a0 = hadd2(p0);
            float a1 = hadd2(p1);
            a0 += __shfl_xor_sync(0xffffffffu, a0, 8);
            a1 += __shfl_xor_sync(0xffffffffu, a1, 8);
            a0 += __shfl_xor_sync(0xffffffffu, a0, 16);
            a1 += __shfl_xor_sync(0xffffffffu, a1, 16);
            if (kh0) {
                x1acc = fmaf(p.attn0[r],     fsigmoid(a0 + b0c), x1acc);
                x1acc = fmaf(p.attn0[r + 1], fsigmoid(a1 + b0c), x1acc);
            }
        }
        uint64_t p16 = 0;
        const float* x0r = p.x0 + kh20;
        #pragma unroll
        for (int q = 0; q < 4; ++q) {
            const ulonglong2 xv = *reinterpret_cast<const ulonglong2*>(x0r + q * 4);
            p16 = fma2(xv.x, Wp[2 * q + 0], p16);
            p16 = fma2(xv.y, Wp[2 * q + 1], p16);
        }
        float a16 = hadd2(p16);
        a16 += __shfl_xor_sync(0xffffffffu, a16, 8);
        a16 += __shfl_xor_sync(0xffffffffu, a16, 16);
        if (kh0) p.x1[((c >> 4) * 20) + (c & 15)] = x1acc + fsigmoid(a16 + b0c);
    }

    // ---- W0 dead: reload Wp with W1 ----
    #pragma unroll
    for (int q = 0; q < 8; ++q)
        Wp[q] = pack2(__ldg(W1g + (kbase + 2 * q) * DIMK + c),
                      __ldg(W1g + (kbase + 2 * q + 1) * DIMK + c));
    __syncthreads();

    // ---- P5: final GEMM + tanh ----
    #pragma unroll
    for (int ii = 0; ii < NITEMS; ++ii) {
        PerItem& p = s.pi[ii];
        uint64_t pa = 0;
        const float* x1r = p.x1 + kh20;
        #pragma unroll
        for (int q = 0; q < 4; ++q) {
            const ulonglong2 xv = *reinterpret_cast<const ulonglong2*>(x1r + q * 4);
            pa = fma2(xv.x, Wp[2 * q + 0], pa);
            pa = fma2(xv.y, Wp[2 * q + 1], pa);
        }
        float acc = hadd2(pa);
        acc += __shfl_xor_sync(0xffffffffu, acc, 8);
        acc += __shfl_xor_sync(0xffffffffu, acc, 16);
        if (kh0) p.outf[c] = tanhf(acc + s.b1[c]);
    }
    __syncthreads();

    // ---- P6: sigmoid(user . item) ----
    if (warp < NITEMS) {
        PerItem& p = s.pi[warp];
        float pp = p.userv[lane] * p.outf[lane] + p.userv[lane + 32] * p.outf[lane + 32];
        #pragma unroll
        for (int off = 16; off > 0; off >>= 1)
            pp += __shfl_xor_sync(0xffffffffu, pp, off);
        if (lane == 0) out[item0 + warp] = fsigmoid(pp);
    }
}

extern "C" void kernel_launch(void* const* d_in, const int* in_sizes, int n_in,
                              void* d_out, int out_size) {
    const int*   u       = (const int*)d_in[0];
    const int*   v       = (const int*)d_in[1];
    const int*   adj     = (const int*)d_in[2];
    const int*   rel_adj = (const int*)d_in[3];
    const float* usr_emb = (const float*)d_in[4];
    const float* ent_emb = (const float*)d_in[5];
    const float* rel_emb = (const float*)d_in[6];
    const float* W0      = (const float*)d_in[7];
    const float* b0      = (const float*)d_in[8];
    const float* W1      = (const float*)d_in[9];
    const float* b1      = (const float*)d_in[10];
    float* outp = (float*)d_out;

    const int na = (BATCH * NRELT + 255) / 256;
    urel_kernel<<<na, 256>>>(u, usr_emb, rel_emb);

    const int smem = (int)sizeof(Smem);
    cudaFuncSetAttribute(kgnn_kernel, cudaFuncAttributeMaxDynamicSharedMemorySize, smem);
    kgnn_kernel<<<GRID, NT, smem>>>(u, v, adj, rel_adj, usr_emb, ent_emb, rel_emb,
                                    W0, b0, W1, b1, outp);
}

// round 17
// speedup vs baseline: 1.0654x; 1.0654x over previous
#include <cuda_runtime.h>
#include <math.h>
#include <stdint.h>

#define DIMK 64
#define NN 16
#define BATCH 4096
#define NRELT 33
#define NT 256
#define NITEMS 2
#define GRID (BATCH / NITEMS)
#define RST 80   // swizzled row stride in floats

struct PerItem {
    float e1v[NN * DIMK];     // 4 KB
    float xbuf[NN * RST];     // 5 KB, swizzled: chunk (kh,q) at float off kh*20+q*4
    float x0[RST];
    float x1[RST];
    float userv[DIMK];
    float e0v[DIMK];
    float outf[DIMK];
    float attn[NN * NN];      // 1 KB
    float urel[NRELT + 3];    // holds exp(user.rel)
    float attn0[NN];
    int   e2[NN * NN];        // 1 KB
    int   r2[NN * NN];        // 1 KB
    int   r1[NN];
};

struct Smem {
    PerItem pi[NITEMS];
    float b0[DIMK];
    float b1[DIMK];
};

__device__ __forceinline__ float fsigmoid(float x) {
    return __fdividef(1.0f, 1.0f + __expf(-x));
}

__device__ __forceinline__ uint64_t fma2(uint64_t a, uint64_t b, uint64_t c) {
    uint64_t d;
    asm("fma.rn.f32x2 %0, %1, %2, %3;" : "=l"(d) : "l"(a), "l"(b), "l"(c));
    return d;
}
__device__ __forceinline__ uint64_t pack2(float lo, float hi) {
    uint64_t d;
    asm("mov.b64 %0, {%1, %2};" : "=l"(d) : "f"(lo), "f"(hi));
    return d;
}
__device__ __forceinline__ float hadd2(uint64_t a) {
    float lo, hi;
    asm("mov.b64 {%0, %1}, %2;" : "=f"(lo), "=f"(hi) : "l"(a));
    return lo + hi;
}

__global__ __launch_bounds__(NT, 6)
void kgnn_kernel(const int* __restrict__ u, const int* __restrict__ v,
                 const int* __restrict__ adj, const int* __restrict__ rel_adj,
                 const float* __restrict__ usr_emb, const float* __restrict__ ent_emb,
                 const float* __restrict__ rel_emb,
                 const float* __restrict__ W0g, const float* __restrict__ b0g,
                 const float* __restrict__ W1g, const float* __restrict__ b1g,
                 float* __restrict__ out)
{
    extern __shared__ char smem_raw[];
    Smem& s = *reinterpret_cast<Smem*>(smem_raw);
    const int tid  = threadIdx.x;
    const int lane = tid & 31;
    const int warp = tid >> 5;
    const int c     = warp * 8 + (lane & 7);
    const int kh    = lane >> 3;
    const int kbase = kh * 16;
    const int kh20  = kh * 20;
    const bool kh0  = (kh == 0);

    const float4* ent4 = reinterpret_cast<const float4*>(ent_emb);
    const ulonglong2* ent8 = reinterpret_cast<const ulonglong2*>(ent_emb);
    const int item0 = blockIdx.x * NITEMS;

    // W0 column-slice packed; later reloaded with W1 (W0 dead after P4)
    uint64_t Wp[8];
    #pragma unroll
    for (int q = 0; q < 8; ++q)
        Wp[q] = pack2(__ldg(W0g + (kbase + 2 * q) * DIMK + c),
                      __ldg(W0g + (kbase + 2 * q + 1) * DIMK + c));
    if (tid < DIMK) { s.b0[tid] = b0g[tid]; s.b1[tid] = b1g[tid]; }
    __syncthreads();

    // ---- P1: indices + e1v staging + root vectors + exp(urel) (both items) ----
    #pragma unroll
    for (int ii = 0; ii < NITEMS; ++ii) {
        PerItem& p = s.pi[ii];
        const int vv = __ldg(v + item0 + ii);
        const int uu = __ldg(u + item0 + ii);
        const int m = tid >> 4, n = tid & 15;
        const int e1m = __ldg(adj + vv * NN + m);
        p.e2[tid] = __ldg(adj + e1m * NN + n);
        p.r2[tid] = __ldg(rel_adj + e1m * NN + n);
        reinterpret_cast<float4*>(p.e1v)[tid] = __ldg(ent4 + e1m * 16 + n);
        if (tid < 16) {
            p.r1[tid] = __ldg(rel_adj + vv * NN + tid);
            reinterpret_cast<float4*>(p.userv)[tid] = __ldg(
                reinterpret_cast<const float4*>(usr_emb) + uu * 16 + tid);
        } else if (tid < 32) {
            reinterpret_cast<float4*>(p.e0v)[tid - 16] = __ldg(ent4 + vv * 16 + (tid - 16));
        }
        const float ua = __ldg(usr_emb + uu * DIMK + lane);
        const float ub = __ldg(usr_emb + uu * DIMK + lane + 32);
        for (int r = warp; r < NRELT; r += 8) {
            float pp = ua * __ldg(rel_emb + r * DIMK + lane)
                     + ub * __ldg(rel_emb + r * DIMK + lane + 32);
            #pragma unroll
            for (int off = 16; off > 0; off >>= 1)
                pp += __shfl_xor_sync(0xffffffffu, pp, off);
            if (lane == 0) p.urel[r] = __expf(pp);   // store exp directly
        }
    }
    __syncthreads();

    // ---- P2: softmax, no max pass (exp precomputed in urel) ----
    #pragma unroll
    for (int ii = 0; ii < NITEMS; ++ii) {
        PerItem& p = s.pi[ii];
        const float e = p.urel[p.r2[tid]];
        float sum = e;
        #pragma unroll
        for (int off = 8; off > 0; off >>= 1)
            sum += __shfl_xor_sync(0xffffffffu, sum, off);
        p.attn[tid] = __fdividef(e, sum);

        if (warp == ii) {
            const float e0 = p.urel[p.r1[lane & 15]];
            float s0 = e0;
            #pragma unroll
            for (int off = 8; off > 0; off >>= 1)
                s0 += __shfl_xor_sync(0xffffffffu, s0, off);
            if (lane < 16) p.attn0[lane] = __fdividef(e0, s0);
        }
    }
    __syncthreads();

    // ---- P3: hop-1 aggregation + x0 on warps 6/7; swizzled stores ----
    #pragma unroll
    for (int ii = 0; ii < NITEMS; ++ii) {
        PerItem& p = s.pi[ii];
        const int m  = warp * 2 + (lane >> 4);
        const int l4 = lane & 15;
        const int swoff = (l4 >> 2) * 20 + (l4 & 3) * 4;
        const int4*   e2v = reinterpret_cast<const int4*>(p.e2 + m * NN);
        const float4* av  = reinterpret_cast<const float4*>(p.attn + m * NN);
        ulonglong2 acc = reinterpret_cast<const ulonglong2*>(p.e1v + m * DIMK)[l4];
        #pragma unroll
        for (int j = 0; j < 4; ++j) {
            const int4   ei = e2v[j];
            const float4 aw = av[j];
            const uint64_t a0 = pack2(aw.x, aw.x);
            const uint64_t a1 = pack2(aw.y, aw.y);
            const uint64_t a2 = pack2(aw.z, aw.z);
            const uint64_t a3 = pack2(aw.w, aw.w);
            const ulonglong2 v0 = __ldg(ent8 + ei.x * 16 + l4);
            const ulonglong2 v1 = __ldg(ent8 + ei.y * 16 + l4);
            const ulonglong2 v2 = __ldg(ent8 + ei.z * 16 + l4);
            const ulonglong2 v3 = __ldg(ent8 + ei.w * 16 + l4);
            acc.x = fma2(a0, v0.x, acc.x); acc.y = fma2(a0, v0.y, acc.y);
            acc.x = fma2(a1, v1.x, acc.x); acc.y = fma2(a1, v1.y, acc.y);
            acc.x = fma2(a2, v2.x, acc.x); acc.y = fma2(a2, v2.y, acc.y);
            acc.x = fma2(a3, v3.x, acc.x); acc.y = fma2(a3, v3.y, acc.y);
        }
        *reinterpret_cast<ulonglong2*>(p.xbuf + m * RST + swoff) = acc;

        if (warp == 6 + ii && lane < 16) {
            ulonglong2 a0v = reinterpret_cast<const ulonglong2*>(p.e0v)[lane];
            #pragma unroll
            for (int n = 0; n < NN; ++n) {
                const ulonglong2 ev = reinterpret_cast<const ulonglong2*>(p.e1v + n * DIMK)[lane];
                const float an = p.attn0[n];
                const uint64_t an2 = pack2(an, an);
                a0v.x = fma2(an2, ev.x, a0v.x);
                a0v.y = fma2(an2, ev.y, a0v.y);
            }
            *reinterpret_cast<ulonglong2*>(p.x0 + swoff) = a0v;
        }
    }
    __syncthreads();

    // ---- P4: fused GEMM ----
    #pragma unroll
    for (int ii = 0; ii < NITEMS; ++ii) {
        PerItem& p = s.pi[ii];
        const float b0c = s.b0[c];
        float x1acc = 0.f;
        #pragma unroll
        for (int r = 0; r < NN; r += 2) {
            uint64_t p0 = 0, p1 = 0;
            const float* xr0 = p.xbuf + r * RST + kh20;
            const float* xr1 = p.xbuf + (r + 1) * RST + kh20;
            #pragma unroll
            for (int q = 0; q < 4; ++q) {
                const ulonglong2 xv0 = *reinterpret_cast<const ulonglong2*>(xr0 + q * 4);
                const ulonglong2 xv1 = *reinterpret_cast<const ulonglong2*>(xr1 + q * 4);
                p0 = fma2(xv0.x, Wp[2 * q + 0], p0);
                p1 = fma2(xv1.x, Wp[2 * q + 0], p1);
                p0 = fma2(xv0.y, Wp[2 * q + 1], p0);
                p1 = fma2(xv1.y, Wp[2 * q + 1], p1);
            }
            float a0 = hadd2(p0);
            float a1 = hadd2(p1);
            a0 += __shfl_xor_sync(0xffffffffu, a0, 8);
            a1 += __shfl_xor_sync(0xffffffffu, a1, 8);
            a0 += __shfl_xor_sync(0xffffffffu, a0, 16);
            a1 += __shfl_xor_sync(0xffffffffu, a1, 16);
            if (kh0) {
                x1acc = fmaf(p.attn0[r],     fsigmoid(a0 + b0c), x1acc);
                x1acc = fmaf(p.attn0[r + 1], fsigmoid(a1 + b0c), x1acc);
            }
        }
        uint64_t p16 = 0;
        const float* x0r = p.x0 + kh20;
        #pragma unroll
        for (int q = 0; q < 4; ++q) {
            const ulonglong2 xv = *reinterpret_cast<const ulonglong2*>(x0r + q * 4);
            p16 = fma2(xv.x, Wp[2 * q + 0], p16);
            p16 = fma2(xv.y, Wp[2 * q + 1], p16);
        }
        float a16 = hadd2(p16);
        a16 += __shfl_xor_sync(0xffffffffu, a16, 8);
        a16 += __shfl_xor_sync(0xffffffffu, a16, 16);
        if (kh0) p.x1[((c >> 4) * 20) + (c & 15)] = x1acc + fsigmoid(a16 + b0c);
    }

    // ---- W0 dead: reload Wp with W1 ----
    #pragma unroll
    for (int q = 0; q < 8; ++q)
        Wp[q] = pack2(__ldg(W1g + (kbase + 2 * q) * DIMK + c),
                      __ldg(W1g + (kbase + 2 * q + 1) * DIMK + c));
    __syncthreads();

    // ---- P5: final GEMM + tanh ----
    #pragma unroll
    for (int ii = 0; ii < NITEMS; ++ii) {
        PerItem& p = s.pi[ii];
        uint64_t pa = 0;
        const float* x1r = p.x1 + kh20;
        #pragma unroll
        for (int q = 0; q < 4; ++q) {
            const ulonglong2 xv = *reinterpret_cast<const ulonglong2*>(x1r + q * 4);
            pa = fma2(xv.x, Wp[2 * q + 0], pa);
            pa = fma2(xv.y, Wp[2 * q + 1], pa);
        }
        float acc = hadd2(pa);
        acc += __shfl_xor_sync(0xffffffffu, acc, 8);
        acc += __shfl_xor_sync(0xffffffffu, acc, 16);
        if (kh0) p.outf[c] = tanhf(acc + s.b1[c]);
    }
    __syncthreads();

    // ---- P6: sigmoid(user . item) ----
    if (warp < NITEMS) {
        PerItem& p = s.pi[warp];
        float pp = p.userv[lane] * p.outf[lane] + p.userv[lane + 32] * p.outf[lane + 32];
        #pragma unroll
        for (int off = 16; off > 0; off >>= 1)
            pp += __shfl_xor_sync(0xffffffffu, pp, off);
        if (lane == 0) out[item0 + warp] = fsigmoid(pp);
    }
}

extern "C" void kernel_launch(void* const* d_in, const int* in_sizes, int n_in,
                              void* d_out, int out_size) {
    const int*   u       = (const int*)d_in[0];
    const int*   v       = (const int*)d_in[1];
    const int*   adj     = (const int*)d_in[2];
    const int*   rel_adj = (const int*)d_in[3];
    const float* usr_emb = (const float*)d_in[4];
    const float* ent_emb = (const float*)d_in[5];
    const float* rel_emb = (const float*)d_in[6];
    const float* W0      = (const float*)d_in[7];
    const float* b0      = (const float*)d_in[8];
    const float* W1      = (const float*)d_in[9];
    const float* b1      = (const float*)d_in[10];
    float* outp = (float*)d_out;

    const int smem = (int)sizeof(Smem);
    cudaFuncSetAttribute(kgnn_kernel, cudaFuncAttributeMaxDynamicSharedMemorySize, smem);
    kgnn_kernel<<<GRID, NT, smem>>>(u, v, adj, rel_adj, usr_emb, ent_emb, rel_emb,
                                    W0, b0, W1, b1, outp);
}